// round 6
// baseline (speedup 1.0000x reference)
#include <cuda_runtime.h>
#include <cstdint>

// ---------------- problem constants ----------------
#define E_TOTAL   500000
#define MT        128          // edges per CTA
#define NTH       512          // threads per CTA (16 warps, 4x4 warp grid)
#define KC        32           // K-chunk for weight panels

// SMEM strides (padded for bank-conflict-free LDS patterns)
#define SA_LD     68           // A staging  [128 x 64] (+4 pad)
#define SH_LD     260          // H buffer   [128 x 256] (+4 pad)
#define SB_LD     264          // W panel    [32 x 256] (+8 pad -> conflict-free B frag loads)

struct Smem {
    float A[MT * SA_LD];       // 34816 B : layer-1 A staging / output staging
    float B[KC * SB_LD];       // 33792 B : weight K-chunk panel
    float H[MT * SH_LD];       // 133120 B: h1 then h2 (fp32)
    int   batch[MT];
    float w0[MT], w1[MT], mu[MT], rs[MT];
    int   is64;
    // parameters
    float Ww[256], bw[128], gw[128], betaw[128];
    float b1[256], g1[256], beta1[256];
    float b2[256], g2[256], beta2[256];
    float b3[64];
};

__device__ __forceinline__ unsigned f2tf32(float x) {
    unsigned u;
    asm("cvt.rna.tf32.f32 %0, %1;" : "=r"(u) : "f"(x));
    return u;
}

__device__ __forceinline__ void mma8(float* d,
                                     unsigned a0, unsigned a1, unsigned a2, unsigned a3,
                                     unsigned b0, unsigned b1) {
    asm volatile(
        "mma.sync.aligned.m16n8k8.row.col.f32.tf32.tf32.f32 "
        "{%0,%1,%2,%3}, {%4,%5,%6,%7}, {%8,%9}, {%0,%1,%2,%3};"
        : "+f"(d[0]), "+f"(d[1]), "+f"(d[2]), "+f"(d[3])
        : "r"(a0), "r"(a1), "r"(a2), "r"(a3), "r"(b0), "r"(b1));
}

// One 32-deep K chunk: A from smem (fp32, row-major, stride lda),
// B from smem weight panel (stride SB_LD). NT n-tiles of 8 cols each.
template <int NT>
__device__ __forceinline__ void mma_chunk(const float* __restrict__ A, int lda,
                                          const float* __restrict__ Bc, int nbase,
                                          float acc[2][8][4], int lane, int wm) {
    const int lr = lane >> 2, lc = lane & 3;
#pragma unroll
    for (int ks = 0; ks < 4; ks++) {
        const int kb = ks * 8;
        unsigned a[2][4];
#pragma unroll
        for (int mt = 0; mt < 2; mt++) {
            const float* ap = A + (wm + mt * 16 + lr) * lda + kb + lc;
            a[mt][0] = f2tf32(ap[0]);
            a[mt][1] = f2tf32(ap[8 * lda]);
            a[mt][2] = f2tf32(ap[4]);
            a[mt][3] = f2tf32(ap[8 * lda + 4]);
        }
#pragma unroll
        for (int nt = 0; nt < NT; nt++) {
            const float* bp = Bc + (kb + lc) * SB_LD + nbase + nt * 8 + lr;
            unsigned b0 = f2tf32(bp[0]);
            unsigned b1 = f2tf32(bp[4 * SB_LD]);
            mma8(acc[0][nt], a[0][0], a[0][1], a[0][2], a[0][3], b0, b1);
            mma8(acc[1][nt], a[1][0], a[1][1], a[1][2], a[1][3], b0, b1);
        }
    }
}

// Load one [KC x N] weight chunk (row-major global) into the SMEM panel (float4).
__device__ __forceinline__ void load_w(float* __restrict__ sB, const float* __restrict__ W,
                                       int kc, int N, int tid) {
    const int nv = KC * N / 4;
    const float4* Wg = reinterpret_cast<const float4*>(W + (size_t)kc * N);
    for (int i = tid; i < nv; i += NTH) {
        int r = (i * 4) / N;
        int c = (i * 4) % N;
        *reinterpret_cast<float4*>(&sB[r * SB_LD + c]) = Wg[i];
    }
}

// Row-wise LayerNorm(+affine)+ReLU in place over H[128 x 256]; 4 threads / row.
__device__ __forceinline__ void ln_relu(float* __restrict__ H,
                                        const float* __restrict__ g,
                                        const float* __restrict__ be, int tid) {
    const int r = tid >> 2, q = tid & 3;
    float* row = H + r * SH_LD;
    float s = 0.f, s2 = 0.f;
#pragma unroll 4
    for (int cc = 0; cc < 64; cc++) {
        float v = row[q * 64 + cc];
        s += v; s2 += v * v;
    }
    s  += __shfl_xor_sync(0xffffffffu, s, 1);
    s2 += __shfl_xor_sync(0xffffffffu, s2, 1);
    s  += __shfl_xor_sync(0xffffffffu, s, 2);
    s2 += __shfl_xor_sync(0xffffffffu, s2, 2);
    float mu  = s * (1.f / 256.f);
    float var = fmaxf(s2 * (1.f / 256.f) - mu * mu, 0.f);
    float rsd = rsqrtf(var + 1e-5f);
#pragma unroll 4
    for (int cc = 0; cc < 64; cc++) {
        int c = q * 64 + cc;
        float v = (row[c] - mu) * rsd * g[c] + be[c];
        row[c] = fmaxf(v, 0.f);
    }
}

// Scatter accumulators (+bias) into H buffer.
__device__ __forceinline__ void store_h(float* __restrict__ H, float acc[2][8][4],
                                        const float* __restrict__ bias,
                                        int wm, int wn, int lane) {
    const int lr = lane >> 2, lc = lane & 3;
#pragma unroll
    for (int mt = 0; mt < 2; mt++)
#pragma unroll
        for (int nt = 0; nt < 8; nt++) {
            int c = wn + nt * 8 + 2 * lc;
#pragma unroll
            for (int h = 0; h < 2; h++) {
                int r = wm + mt * 16 + lr + h * 8;
                H[r * SH_LD + c]     = acc[mt][nt][2 * h]     + bias[c];
                H[r * SH_LD + c + 1] = acc[mt][nt][2 * h + 1] + bias[c + 1];
            }
        }
}

__global__ void __launch_bounds__(NTH, 1)
edge_mlp_kernel(const float* __restrict__ src, const float* __restrict__ dst,
                const float* __restrict__ ea, const float* __restrict__ u,
                const void* __restrict__ batch_raw, const float* __restrict__ wind,
                const float* __restrict__ Ww, const float* __restrict__ bw,
                const float* __restrict__ gw, const float* __restrict__ betaw,
                const float* __restrict__ W1, const float* __restrict__ b1,
                const float* __restrict__ g1, const float* __restrict__ beta1,
                const float* __restrict__ W2, const float* __restrict__ b2,
                const float* __restrict__ g2, const float* __restrict__ beta2,
                const float* __restrict__ W3, const float* __restrict__ b3,
                float* __restrict__ out) {
    extern __shared__ char smem_raw[];
    Smem& sm = *reinterpret_cast<Smem*>(smem_raw);

    const int tid  = threadIdx.x;
    const int lane = tid & 31;
    const int warp = tid >> 5;
    const int wm   = (warp >> 2) * 32;   // warp row base (0/32/64/96)
    const int wcol = warp & 3;           // warp col (0..3)
    const long long base = (long long)blockIdx.x * MT;

    // ---- batch dtype autodetect (int64 has zero high words; int32 data doesn't) ----
    if (tid == 0) {
        const unsigned* p = reinterpret_cast<const unsigned*>(batch_raw);
        int f = 1;
        for (int i = 0; i < 64; i++)
            if (p[2 * i + 1] != 0u) { f = 0; break; }
        sm.is64 = f;
    }

    // ---- parameters -> smem ----
    for (int i = tid; i < 256; i += NTH) sm.Ww[i] = Ww[i];
    for (int i = tid; i < 128; i += NTH) {
        sm.bw[i] = bw[i]; sm.gw[i] = gw[i]; sm.betaw[i] = betaw[i];
    }
    for (int i = tid; i < 256; i += NTH) {
        sm.b1[i] = b1[i]; sm.g1[i] = g1[i]; sm.beta1[i] = beta1[i];
        sm.b2[i] = b2[i]; sm.g2[i] = g2[i]; sm.beta2[i] = beta2[i];
    }
    for (int i = tid; i < 64; i += NTH) sm.b3[i] = b3[i];
    __syncthreads();

    // ---- per-edge scalars ----
    const int is64 = sm.is64;
    for (int r = tid; r < MT; r += NTH) {
        long long e = base + r;
        if (e < E_TOTAL) {
            sm.batch[r] = is64 ? (int)reinterpret_cast<const long long*>(batch_raw)[e]
                               : reinterpret_cast<const int*>(batch_raw)[e];
            sm.w0[r] = wind[2 * e];
            sm.w1[r] = wind[2 * e + 1];
        } else {
            sm.batch[r] = 0; sm.w0[r] = 0.f; sm.w1[r] = 0.f;
        }
    }
    __syncthreads();

    // ---- winding-MLP LN stats (mu, rstd) per edge; w regenerated on the fly later ----
    {
        const int r = tid >> 2, q = tid & 3;
        const float a0 = sm.w0[r], a1 = sm.w1[r];
        float s = 0.f, s2 = 0.f;
#pragma unroll 4
        for (int jj = 0; jj < 32; jj++) {
            int j = q * 32 + jj;
            float t = fmaf(a0, sm.Ww[j], fmaf(a1, sm.Ww[128 + j], sm.bw[j]));
            s += t; s2 += t * t;
        }
        s  += __shfl_xor_sync(0xffffffffu, s, 1);
        s2 += __shfl_xor_sync(0xffffffffu, s2, 1);
        s  += __shfl_xor_sync(0xffffffffu, s, 2);
        s2 += __shfl_xor_sync(0xffffffffu, s2, 2);
        float mu  = s * (1.f / 128.f);
        float var = fmaxf(s2 * (1.f / 128.f) - mu * mu, 0.f);
        if (q == 0) { sm.mu[r] = mu; sm.rs[r] = rsqrtf(var + 1e-5f); }
    }
    __syncthreads();

    float acc[2][8][4];

    // =============== Layer 1: h1 = ReLU(LN(x @ W1 + b1)),  K = 384 ===============
#pragma unroll
    for (int mt = 0; mt < 2; mt++)
#pragma unroll
        for (int nt = 0; nt < 8; nt++)
#pragma unroll
            for (int k = 0; k < 4; k++) acc[mt][nt][k] = 0.f;

    for (int seg = 0; seg < 6; seg++) {
        // Fill A staging [128 x 64] for this K segment.
        for (int i = tid; i < MT * 64; i += NTH) {
            int r = i >> 6, c = i & 63;
            long long e = base + r;
            float v = 0.f;
            if (e < E_TOTAL) {
                if (seg == 0)      v = src[e * 64 + c];
                else if (seg == 1) v = dst[e * 64 + c];
                else if (seg == 2) v = ea[e * 64 + c];
                else if (seg == 3) v = u[sm.batch[r] * 64 + c];
                else {
                    int j   = c + (seg - 4) * 64;
                    float t = fmaf(sm.w0[r], sm.Ww[j], fmaf(sm.w1[r], sm.Ww[128 + j], sm.bw[j]));
                    v = fmaxf((t - sm.mu[r]) * sm.rs[r] * sm.gw[j] + sm.betaw[j], 0.f);
                }
            }
            sm.A[r * SA_LD + c] = v;
        }
        for (int sub = 0; sub < 2; sub++) {
            load_w(sm.B, W1, seg * 64 + sub * 32, 256, tid);
            __syncthreads();  // A + W panel ready
            mma_chunk<8>(sm.A + sub * 32, SA_LD, sm.B, wcol * 64, acc, lane, wm);
            __syncthreads();  // WAR on A / W panel
        }
    }
    store_h(sm.H, acc, sm.b1, wm, wcol * 64, lane);
    __syncthreads();
    ln_relu(sm.H, sm.g1, sm.beta1, tid);
    __syncthreads();

    // =============== Layer 2: h2 = ReLU(LN(h1 @ W2 + b2)), K = 256 ===============
#pragma unroll
    for (int mt = 0; mt < 2; mt++)
#pragma unroll
        for (int nt = 0; nt < 8; nt++)
#pragma unroll
            for (int k = 0; k < 4; k++) acc[mt][nt][k] = 0.f;

    for (int sub = 0; sub < 8; sub++) {
        load_w(sm.B, W2, sub * 32, 256, tid);
        __syncthreads();
        mma_chunk<8>(sm.H + sub * 32, SH_LD, sm.B, wcol * 64, acc, lane, wm);
        __syncthreads();
    }
    store_h(sm.H, acc, sm.b2, wm, wcol * 64, lane);  // safe: all h1 reads done pre-sync
    __syncthreads();
    ln_relu(sm.H, sm.g2, sm.beta2, tid);
    __syncthreads();

    // =============== Layer 3: out = h2 @ W3 + b3, K = 256, N = 64 ===============
#pragma unroll
    for (int mt = 0; mt < 2; mt++)
#pragma unroll
        for (int nt = 0; nt < 2; nt++)
#pragma unroll
            for (int k = 0; k < 4; k++) acc[mt][nt][k] = 0.f;

    for (int sub = 0; sub < 8; sub++) {
        load_w(sm.B, W3, sub * 32, 64, tid);
        __syncthreads();
        mma_chunk<2>(sm.H + sub * 32, SH_LD, sm.B, wcol * 16, acc, lane, wm);
        __syncthreads();
    }
    // Stage output tile into sm.A (cols 0..63), then coalesced global store.
    {
        const int lr = lane >> 2, lc = lane & 3;
#pragma unroll
        for (int mt = 0; mt < 2; mt++)
#pragma unroll
            for (int nt = 0; nt < 2; nt++) {
                int c = wcol * 16 + nt * 8 + 2 * lc;
#pragma unroll
                for (int h = 0; h < 2; h++) {
                    int r = wm + mt * 16 + lr + h * 8;
                    sm.A[r * SA_LD + c]     = acc[mt][nt][2 * h]     + sm.b3[c];
                    sm.A[r * SA_LD + c + 1] = acc[mt][nt][2 * h + 1] + sm.b3[c + 1];
                }
            }
    }
    __syncthreads();
    for (int i = tid; i < MT * 64; i += NTH) {
        int r = i >> 6, c = i & 63;
        long long e = base + r;
        if (e < E_TOTAL) out[e * 64 + c] = sm.A[r * SA_LD + c];
    }
}

extern "C" void kernel_launch(void* const* d_in, const int* in_sizes, int n_in,
                              void* d_out, int out_size) {
    const float* src    = (const float*)d_in[0];
    const float* dst    = (const float*)d_in[1];
    const float* ea     = (const float*)d_in[2];
    const float* u      = (const float*)d_in[3];
    const void*  batch  = d_in[4];                 // int32 or int64: autodetected
    const float* wind   = (const float*)d_in[5];
    const float* Ww     = (const float*)d_in[6];
    const float* bw     = (const float*)d_in[7];
    const float* gw     = (const float*)d_in[8];
    const float* betaw  = (const float*)d_in[9];
    const float* W1     = (const float*)d_in[10];
    const float* b1     = (const float*)d_in[11];
    const float* g1     = (const float*)d_in[12];
    const float* beta1  = (const float*)d_in[13];
    const float* W2     = (const float*)d_in[14];
    const float* b2     = (const float*)d_in[15];
    const float* g2     = (const float*)d_in[16];
    const float* beta2  = (const float*)d_in[17];
    const float* W3     = (const float*)d_in[18];
    const float* b3     = (const float*)d_in[19];
    float* out = (float*)d_out;

    const int smem = (int)sizeof(Smem);
    cudaFuncSetAttribute(edge_mlp_kernel, cudaFuncAttributeMaxDynamicSharedMemorySize, smem);

    const int grid = (E_TOTAL + MT - 1) / MT;
    edge_mlp_kernel<<<grid, NTH, smem>>>(src, dst, ea, u, batch, wind,
                                         Ww, bw, gw, betaw,
                                         W1, b1, g1, beta1,
                                         W2, b2, g2, beta2,
                                         W3, b3, out);
}

// round 9
// speedup vs baseline: 1.2353x; 1.2353x over previous
#include <cuda_runtime.h>
#include <cstdint>

// ---------------- problem constants ----------------
#define E_TOTAL   500000
#define MT        128          // edges per CTA
#define NTH       512          // 16 warps, 4x4 warp grid
#define PW        36           // padded words per n-column in weight panel
#define PANEL_BIG (256 * PW)   // 9216 words (layers 1/2)
#define PANEL_SM  (64 * PW)    // 2304 words (layer 3)
#define SA_LD     68           // layer-1 A staging row stride (words)
#define SH_LD     260          // H buffer row stride (words)

// -------- pre-permuted tf32 weights (written once by prep kernel) --------
__device__ __align__(16) unsigned g_Wp1[12 * PANEL_BIG];
__device__ __align__(16) unsigned g_Wp2[8 * PANEL_BIG];
__device__ __align__(16) unsigned g_Wp3[8 * PANEL_SM];

struct Smem {
    float    H[MT * SH_LD];        // 133120 B; also aliases layer-1 A[2] staging + out staging
    unsigned Wp[2][PANEL_BIG];     // 73728 B : double-buffered weight panels
    float    red[MT][4][2];        // 4096 B : per-row per-warpcol (sum, sumsq)
    int      batch[MT];
    float    w0[MT], w1[MT], mu[MT], rs[MT];
    int      is64;
    float    Ww[256], bw[128], gw[128], betaw[128];
    float    b1[256], g1[256], be1[256];
    float    b2[256], g2[256], be2[256];
    float    b3[64];
};

__device__ __forceinline__ unsigned f2tf32(float x) {
    unsigned u;
    asm("cvt.rna.tf32.f32 %0, %1;" : "=r"(u) : "f"(x));
    return u;
}

__device__ __forceinline__ void mma8(float* d,
                                     unsigned a0, unsigned a1, unsigned a2, unsigned a3,
                                     unsigned b0, unsigned b1) {
    asm volatile(
        "mma.sync.aligned.m16n8k8.row.col.f32.tf32.tf32.f32 "
        "{%0,%1,%2,%3}, {%4,%5,%6,%7}, {%8,%9}, {%0,%1,%2,%3};"
        : "+f"(d[0]), "+f"(d[1]), "+f"(d[2]), "+f"(d[3])
        : "r"(a0), "r"(a1), "r"(a2), "r"(a3), "r"(b0), "r"(b1));
}

// ---------------- weight pre-pass: permute + tf32-convert ----------------
// Layout per 32-K chunk: [n][lc][j] (PW-padded), k = 4*j + lc within chunk.
__global__ void prep_kernel(const float* __restrict__ W1, const float* __restrict__ W2,
                            const float* __restrict__ W3) {
    int tid = blockIdx.x * blockDim.x + threadIdx.x;
    int stride = gridDim.x * blockDim.x;
    for (int i = tid; i < 12 * PANEL_BIG; i += stride) {
        int c = i / PANEL_BIG, rem = i % PANEL_BIG;
        int n = rem / PW, pos = rem % PW;
        unsigned v = 0u;
        if (pos < 32) { int lc = pos >> 3, j = pos & 7; v = f2tf32(W1[(c * 32 + 4 * j + lc) * 256 + n]); }
        g_Wp1[i] = v;
    }
    for (int i = tid; i < 8 * PANEL_BIG; i += stride) {
        int c = i / PANEL_BIG, rem = i % PANEL_BIG;
        int n = rem / PW, pos = rem % PW;
        unsigned v = 0u;
        if (pos < 32) { int lc = pos >> 3, j = pos & 7; v = f2tf32(W2[(c * 32 + 4 * j + lc) * 256 + n]); }
        g_Wp2[i] = v;
    }
    for (int i = tid; i < 8 * PANEL_SM; i += stride) {
        int c = i / PANEL_SM, rem = i % PANEL_SM;
        int n = rem / PW, pos = rem % PW;
        unsigned v = 0u;
        if (pos < 32) { int lc = pos >> 3, j = pos & 7; v = f2tf32(W3[(c * 32 + 4 * j + lc) * 64 + n]); }
        g_Wp3[i] = v;
    }
}

// ---------------- cp.async panel streaming ----------------
__device__ __forceinline__ void issue_panel(Smem& sm, int p, int tid) {
    const unsigned* src;
    int words;
    if (p < 12)      { src = g_Wp1 + p * PANEL_BIG;        words = PANEL_BIG; }
    else if (p < 20) { src = g_Wp2 + (p - 12) * PANEL_BIG; words = PANEL_BIG; }
    else             { src = g_Wp3 + (p - 20) * PANEL_SM;  words = PANEL_SM;  }
    unsigned dstb = (unsigned)__cvta_generic_to_shared(sm.Wp[p & 1]);
    for (int i = tid * 4; i < words; i += NTH * 4) {
        asm volatile("cp.async.cg.shared.global [%0], [%1], 16;"
                     :: "r"(dstb + (unsigned)i * 4u), "l"(src + i));
    }
    asm volatile("cp.async.commit_group;");
}
#define CPWAIT(N) asm volatile("cp.async.wait_group %0;" :: "n"(N))

// ---------------- mma over one 32-K chunk, fragment-major LDS.128 loads ---
template <int NT, bool CVT>
__device__ __forceinline__ void mma_chunk2(const void* __restrict__ Abase, int lda,
                                           const unsigned* __restrict__ Bp, int nbase,
                                           float (*acc)[8][4], int lane, int wm) {
    const int lr = lane >> 2, lc = lane & 3;
    unsigned a[2][2][8];
#pragma unroll
    for (int mt = 0; mt < 2; mt++)
#pragma unroll
        for (int h = 0; h < 2; h++) {
            int row = wm + mt * 16 + h * 8 + lr;
            if (CVT) {
                const float* ap = (const float*)Abase + row * lda + lc * 8;
                float4 v0 = *(const float4*)ap;
                float4 v1 = *(const float4*)(ap + 4);
                a[mt][h][0] = f2tf32(v0.x); a[mt][h][1] = f2tf32(v0.y);
                a[mt][h][2] = f2tf32(v0.z); a[mt][h][3] = f2tf32(v0.w);
                a[mt][h][4] = f2tf32(v1.x); a[mt][h][5] = f2tf32(v1.y);
                a[mt][h][6] = f2tf32(v1.z); a[mt][h][7] = f2tf32(v1.w);
            } else {
                const unsigned* ap = (const unsigned*)Abase + row * lda + lc * 8;
                uint4 v0 = *(const uint4*)ap;
                uint4 v1 = *(const uint4*)(ap + 4);
                a[mt][h][0] = v0.x; a[mt][h][1] = v0.y; a[mt][h][2] = v0.z; a[mt][h][3] = v0.w;
                a[mt][h][4] = v1.x; a[mt][h][5] = v1.y; a[mt][h][6] = v1.z; a[mt][h][7] = v1.w;
            }
        }
#pragma unroll
    for (int nt = 0; nt < NT; nt++) {
        const unsigned* bp = Bp + (nbase + nt * 8 + lr) * PW + lc * 8;
        uint4 b0 = *(const uint4*)bp;
        uint4 b1 = *(const uint4*)(bp + 4);
        unsigned bb[8] = {b0.x, b0.y, b0.z, b0.w, b1.x, b1.y, b1.z, b1.w};
#pragma unroll
        for (int ks = 0; ks < 4; ks++) {
            mma8(acc[0][nt], a[0][0][2*ks], a[0][1][2*ks], a[0][0][2*ks+1], a[0][1][2*ks+1],
                 bb[2*ks], bb[2*ks+1]);
            mma8(acc[1][nt], a[1][0][2*ks], a[1][1][2*ks], a[1][0][2*ks+1], a[1][1][2*ks+1],
                 bb[2*ks], bb[2*ks+1]);
        }
    }
}

// position of true column c within a permuted 256-wide row
__device__ __forceinline__ int permpos(int c) {
    return (c & ~31) + ((c & 3) << 3) + ((c & 31) >> 2);
}

// per-row partial stats from accumulators (includes bias); reduce over lc lanes
__device__ __forceinline__ void stats_from_acc(Smem& sm, float acc[2][8][4],
                                               const float* __restrict__ bias,
                                               int wm, int wn, int wcol, int lane) {
    const int lr = lane >> 2, lc = lane & 3;
#pragma unroll
    for (int mt = 0; mt < 2; mt++)
#pragma unroll
        for (int h = 0; h < 2; h++) {
            float s = 0.f, s2 = 0.f;
#pragma unroll
            for (int nt = 0; nt < 8; nt++) {
                int c = wn + nt * 8 + 2 * lc;
                float v0 = acc[mt][nt][2*h]     + bias[c];
                float v1 = acc[mt][nt][2*h + 1] + bias[c + 1];
                s += v0 + v1; s2 += v0 * v0 + v1 * v1;
            }
            s  += __shfl_xor_sync(0xffffffffu, s, 1);
            s2 += __shfl_xor_sync(0xffffffffu, s2, 1);
            s  += __shfl_xor_sync(0xffffffffu, s, 2);
            s2 += __shfl_xor_sync(0xffffffffu, s2, 2);
            if (lc == 0) {
                int row = wm + mt * 16 + h * 8 + lr;
                sm.red[row][wcol][0] = s;
                sm.red[row][wcol][1] = s2;
            }
        }
}

// write LN(acc+bias)*g+be, ReLU'd, into H at permuted positions
__device__ __forceinline__ void store_h_ln(Smem& sm, float acc[2][8][4],
                                           const float* __restrict__ bias,
                                           const float* __restrict__ g,
                                           const float* __restrict__ be,
                                           int wm, int wn, int lane) {
    const int lr = lane >> 2, lc = lane & 3;
#pragma unroll
    for (int mt = 0; mt < 2; mt++)
#pragma unroll
        for (int h = 0; h < 2; h++) {
            int row = wm + mt * 16 + h * 8 + lr;
            float s  = sm.red[row][0][0] + sm.red[row][1][0] + sm.red[row][2][0] + sm.red[row][3][0];
            float s2 = sm.red[row][0][1] + sm.red[row][1][1] + sm.red[row][2][1] + sm.red[row][3][1];
            float mu  = s * (1.f / 256.f);
            float var = fmaxf(s2 * (1.f / 256.f) - mu * mu, 0.f);
            float rsd = rsqrtf(var + 1e-5f);
            float* Hrow = sm.H + row * SH_LD;
#pragma unroll
            for (int nt = 0; nt < 8; nt++) {
                int c = wn + nt * 8 + 2 * lc;
                int p0 = permpos(c);
                float v0 = (acc[mt][nt][2*h]     + bias[c]     - mu) * rsd * g[c]     + be[c];
                float v1 = (acc[mt][nt][2*h + 1] + bias[c + 1] - mu) * rsd * g[c + 1] + be[c + 1];
                Hrow[p0]     = fmaxf(v0, 0.f);
                Hrow[p0 + 8] = fmaxf(v1, 0.f);
            }
        }
}

__global__ void __launch_bounds__(NTH, 1)
edge_mlp_kernel(const float* __restrict__ src, const float* __restrict__ dst,
                const float* __restrict__ ea, const float* __restrict__ u,
                const void* __restrict__ batch_raw, const float* __restrict__ wind,
                const float* __restrict__ Ww, const float* __restrict__ bw,
                const float* __restrict__ gw, const float* __restrict__ betaw,
                const float* __restrict__ b1, const float* __restrict__ g1,
                const float* __restrict__ beta1,
                const float* __restrict__ b2, const float* __restrict__ g2,
                const float* __restrict__ beta2,
                const float* __restrict__ b3,
                float* __restrict__ out) {
    extern __shared__ char smem_raw[];
    Smem& sm = *reinterpret_cast<Smem*>(smem_raw);

    const int tid  = threadIdx.x;
    const int lane = tid & 31;
    const int warp = tid >> 5;
    const int wm   = (warp >> 2) * 32;
    const int wcol = warp & 3;
    const long long base = (long long)blockIdx.x * MT;

    // prefetch first two weight panels immediately
    issue_panel(sm, 0, tid);
    issue_panel(sm, 1, tid);

    if (tid == 0) {
        const unsigned* p = reinterpret_cast<const unsigned*>(batch_raw);
        int f = 1;
        for (int i = 0; i < 64; i++)
            if (p[2 * i + 1] != 0u) { f = 0; break; }
        sm.is64 = f;
    }
    for (int i = tid; i < 256; i += NTH) sm.Ww[i] = Ww[i];
    for (int i = tid; i < 128; i += NTH) { sm.bw[i] = bw[i]; sm.gw[i] = gw[i]; sm.betaw[i] = betaw[i]; }
    for (int i = tid; i < 256; i += NTH) {
        sm.b1[i] = b1[i]; sm.g1[i] = g1[i]; sm.be1[i] = beta1[i];
        sm.b2[i] = b2[i]; sm.g2[i] = g2[i]; sm.be2[i] = beta2[i];
    }
    for (int i = tid; i < 64; i += NTH) sm.b3[i] = b3[i];
    __syncthreads();

    const int is64 = sm.is64;
    for (int r = tid; r < MT; r += NTH) {
        long long e = base + r;
        if (e < E_TOTAL) {
            sm.batch[r] = is64 ? (int)reinterpret_cast<const long long*>(batch_raw)[e]
                               : reinterpret_cast<const int*>(batch_raw)[e];
            sm.w0[r] = wind[2 * e];
            sm.w1[r] = wind[2 * e + 1];
        } else { sm.batch[r] = 0; sm.w0[r] = 0.f; sm.w1[r] = 0.f; }
    }
    __syncthreads();

    // winding-MLP LN stats
    {
        const int r = tid >> 2, q = tid & 3;
        const float a0 = sm.w0[r], a1 = sm.w1[r];
        float s = 0.f, s2 = 0.f;
#pragma unroll 4
        for (int jj = 0; jj < 32; jj++) {
            int j = q * 32 + jj;
            float t = fmaf(a0, sm.Ww[j], fmaf(a1, sm.Ww[128 + j], sm.bw[j]));
            s += t; s2 += t * t;
        }
        s  += __shfl_xor_sync(0xffffffffu, s, 1);
        s2 += __shfl_xor_sync(0xffffffffu, s2, 1);
        s  += __shfl_xor_sync(0xffffffffu, s, 2);
        s2 += __shfl_xor_sync(0xffffffffu, s2, 2);
        float mu  = s * (1.f / 128.f);
        float var = fmaxf(s2 * (1.f / 128.f) - mu * mu, 0.f);
        if (q == 0) { sm.mu[r] = mu; sm.rs[r] = rsqrtf(var + 1e-5f); }
    }
    __syncthreads();

    // ---- layer-1 A staging (permuted + tf32 bits), double-buffered over H ----
    auto stageA = [&](int seg) {
        unsigned* A = reinterpret_cast<unsigned*>(sm.H) + (seg & 1) * (MT * SA_LD);
        for (int i = tid; i < MT * 64; i += NTH) {
            int r = i >> 6, c = i & 63;
            long long e = base + r;
            float v = 0.f;
            if (e < E_TOTAL) {
                if (seg == 0)      v = src[e * 64 + c];
                else if (seg == 1) v = dst[e * 64 + c];
                else if (seg == 2) v = ea[e * 64 + c];
                else if (seg == 3) v = u[sm.batch[r] * 64 + c];
                else {
                    int j = c + (seg - 4) * 64;
                    float t = fmaf(sm.w0[r], sm.Ww[j], fmaf(sm.w1[r], sm.Ww[128 + j], sm.bw[j]));
                    v = fmaxf((t - sm.mu[r]) * sm.rs[r] * sm.gw[j] + sm.betaw[j], 0.f);
                }
            }
            int pos = (c & 32) + ((c & 3) << 3) + ((c & 31) >> 2);
            A[r * SA_LD + pos] = f2tf32(v);
        }
    };
    stageA(0);
    stageA(1);

    float acc[2][8][4];

    // =============== Layer 1: K=384, 12 chunks ===============
#pragma unroll
    for (int mt = 0; mt < 2; mt++)
#pragma unroll
        for (int nt = 0; nt < 8; nt++)
#pragma unroll
            for (int k = 0; k < 4; k++) acc[mt][nt][k] = 0.f;

    for (int t = 0; t < 12; t++) {
        CPWAIT(1);
        __syncthreads();
        const unsigned* Ab = reinterpret_cast<const unsigned*>(sm.H)
                             + ((t >> 1) & 1) * (MT * SA_LD) + (t & 1) * 32;
        mma_chunk2<8, false>(Ab, SA_LD, sm.Wp[t & 1], wcol * 64, acc, lane, wm);
        __syncthreads();
        issue_panel(sm, t + 2, tid);
        if ((t & 1) && ((t >> 1) + 2) <= 5) stageA((t >> 1) + 2);
    }
    stats_from_acc(sm, acc, sm.b1, wm, wcol * 64, wcol, lane);
    __syncthreads();
    store_h_ln(sm, acc, sm.b1, sm.g1, sm.be1, wm, wcol * 64, lane);
    __syncthreads();

    // =============== Layer 2: K=256, 8 chunks ===============
#pragma unroll
    for (int mt = 0; mt < 2; mt++)
#pragma unroll
        for (int nt = 0; nt < 8; nt++)
#pragma unroll
            for (int k = 0; k < 4; k++) acc[mt][nt][k] = 0.f;

    for (int t = 0; t < 8; t++) {
        int p = 12 + t;
        CPWAIT(1);
        __syncthreads();
        mma_chunk2<8, true>(sm.H + t * 32, SH_LD, sm.Wp[p & 1], wcol * 64, acc, lane, wm);
        __syncthreads();
        issue_panel(sm, p + 2, tid);
    }
    stats_from_acc(sm, acc, sm.b2, wm, wcol * 64, wcol, lane);
    __syncthreads();
    store_h_ln(sm, acc, sm.b2, sm.g2, sm.be2, wm, wcol * 64, lane);
    __syncthreads();

    // =============== Layer 3: K=256, N=64, 8 chunks ===============
#pragma unroll
    for (int mt = 0; mt < 2; mt++)
#pragma unroll
        for (int nt = 0; nt < 2; nt++)
#pragma unroll
            for (int k = 0; k < 4; k++) acc[mt][nt][k] = 0.f;

    for (int t = 0; t < 8; t++) {
        int p = 20 + t;
        if (p == 27) { CPWAIT(0); } else { CPWAIT(1); }
        __syncthreads();
        mma_chunk2<2, true>(sm.H + t * 32, SH_LD, sm.Wp[p & 1], wcol * 16, acc, lane, wm);
        __syncthreads();
        if (p + 2 < 28) issue_panel(sm, p + 2, tid);
    }
    // stage output (unpermuted, stride SA_LD) over H, then coalesced float4 store
    {
        const int lr = lane >> 2, lc = lane & 3;
#pragma unroll
        for (int mt = 0; mt < 2; mt++)
#pragma unroll
            for (int nt = 0; nt < 2; nt++) {
                int c = wcol * 16 + nt * 8 + 2 * lc;
#pragma unroll
                for (int h = 0; h < 2; h++) {
                    int r = wm + mt * 16 + lr + h * 8;
                    sm.H[r * SA_LD + c]     = acc[mt][nt][2*h]     + sm.b3[c];
                    sm.H[r * SA_LD + c + 1] = acc[mt][nt][2*h + 1] + sm.b3[c + 1];
                }
            }
    }
    __syncthreads();
    for (int i = tid; i < MT * 16; i += NTH) {
        int r = i >> 4, c4 = i & 15;
        long long e = base + r;
        if (e < E_TOTAL) {
            float4 v = *reinterpret_cast<const float4*>(sm.H + r * SA_LD + c4 * 4);
            *reinterpret_cast<float4*>(out + e * 64 + c4 * 4) = v;
        }
    }
}

extern "C" void kernel_launch(void* const* d_in, const int* in_sizes, int n_in,
                              void* d_out, int out_size) {
    const float* src    = (const float*)d_in[0];
    const float* dst    = (const float*)d_in[1];
    const float* ea     = (const float*)d_in[2];
    const float* u      = (const float*)d_in[3];
    const void*  batch  = d_in[4];
    const float* wind   = (const float*)d_in[5];
    const float* Ww     = (const float*)d_in[6];
    const float* bw     = (const float*)d_in[7];
    const float* gw     = (const float*)d_in[8];
    const float* betaw  = (const float*)d_in[9];
    const float* W1     = (const float*)d_in[10];
    const float* b1     = (const float*)d_in[11];
    const float* g1     = (const float*)d_in[12];
    const float* beta1  = (const float*)d_in[13];
    const float* W2     = (const float*)d_in[14];
    const float* b2     = (const float*)d_in[15];
    const float* g2     = (const float*)d_in[16];
    const float* beta2  = (const float*)d_in[17];
    const float* W3     = (const float*)d_in[18];
    const float* b3     = (const float*)d_in[19];
    float* out = (float*)d_out;

    prep_kernel<<<296, 256>>>(W1, W2, W3);

    const int smem = (int)sizeof(Smem);
    cudaFuncSetAttribute(edge_mlp_kernel, cudaFuncAttributeMaxDynamicSharedMemorySize, smem);
    const int grid = (E_TOTAL + MT - 1) / MT;
    edge_mlp_kernel<<<grid, NTH, smem>>>(src, dst, ea, u, batch, wind,
                                         Ww, bw, gw, betaw,
                                         b1, g1, beta1,
                                         b2, g2, beta2,
                                         b3, out);
}

// round 11
// speedup vs baseline: 1.3123x; 1.0623x over previous
#include <cuda_runtime.h>
#include <cstdint>

// ---------------- problem constants ----------------
#define E_TOTAL   500000
#define MT        128          // edges per CTA
#define NTH       256          // 8 warps, 2x4 warp grid (64x64 per warp)
#define PW        36           // padded words per n-column in weight panel
#define PANEL_BIG (256 * PW)   // 9216 words (layers 1/2)
#define PANEL_SM  (64 * PW)    // 2304 words (layer 3)
#define SA_LD     68           // layer-1 A staging row stride (words)
#define SH_LD     260          // H buffer row stride (words)

// -------- pre-permuted tf32 weights (written once by prep kernel) --------
__device__ __align__(16) unsigned g_Wp1[12 * PANEL_BIG];
__device__ __align__(16) unsigned g_Wp2[8 * PANEL_BIG];
__device__ __align__(16) unsigned g_Wp3[8 * PANEL_SM];

struct Smem {
    float    H[MT * SH_LD];        // 133120 B; aliases layer-1 A[2] staging + out staging
    unsigned Wp[2][PANEL_BIG];     // 73728 B : double-buffered weight panels
    float    red[MT][4][2];        // per-row per-warpcol (sum, sumsq)
    int      batch[MT];
    float    w0[MT], w1[MT], mu[MT], rs[MT];
    int      is64;
    float    Ww[256], bw[128], gw[128], betaw[128];
    float    b1[256], g1[256], be1[256];
    float    b2[256], g2[256], be2[256];
    float    b3[64];
};

__device__ __forceinline__ unsigned f2tf32(float x) {
    unsigned u;
    asm("cvt.rna.tf32.f32 %0, %1;" : "=r"(u) : "f"(x));
    return u;
}

__device__ __forceinline__ void mma8(float* d,
                                     unsigned a0, unsigned a1, unsigned a2, unsigned a3,
                                     unsigned b0, unsigned b1) {
    asm volatile(
        "mma.sync.aligned.m16n8k8.row.col.f32.tf32.tf32.f32 "
        "{%0,%1,%2,%3}, {%4,%5,%6,%7}, {%8,%9}, {%0,%1,%2,%3};"
        : "+f"(d[0]), "+f"(d[1]), "+f"(d[2]), "+f"(d[3])
        : "r"(a0), "r"(a1), "r"(a2), "r"(a3), "r"(b0), "r"(b1));
}

// ---------------- weight pre-pass: permute + tf32-convert ----------------
// Layout per 32-K chunk: [n][lc][j] (PW-padded), k = 4*j + lc within chunk.
__global__ void prep_kernel(const float* __restrict__ W1, const float* __restrict__ W2,
                            const float* __restrict__ W3) {
    int tid = blockIdx.x * blockDim.x + threadIdx.x;
    int stride = gridDim.x * blockDim.x;
    for (int i = tid; i < 12 * PANEL_BIG; i += stride) {
        int c = i / PANEL_BIG, rem = i % PANEL_BIG;
        int n = rem / PW, pos = rem % PW;
        unsigned v = 0u;
        if (pos < 32) { int lc = pos >> 3, j = pos & 7; v = f2tf32(W1[(c * 32 + 4 * j + lc) * 256 + n]); }
        g_Wp1[i] = v;
    }
    for (int i = tid; i < 8 * PANEL_BIG; i += stride) {
        int c = i / PANEL_BIG, rem = i % PANEL_BIG;
        int n = rem / PW, pos = rem % PW;
        unsigned v = 0u;
        if (pos < 32) { int lc = pos >> 3, j = pos & 7; v = f2tf32(W2[(c * 32 + 4 * j + lc) * 256 + n]); }
        g_Wp2[i] = v;
    }
    for (int i = tid; i < 8 * PANEL_SM; i += stride) {
        int c = i / PANEL_SM, rem = i % PANEL_SM;
        int n = rem / PW, pos = rem % PW;
        unsigned v = 0u;
        if (pos < 32) { int lc = pos >> 3, j = pos & 7; v = f2tf32(W3[(c * 32 + 4 * j + lc) * 64 + n]); }
        g_Wp3[i] = v;
    }
}

// ---------------- cp.async panel streaming ----------------
__device__ __forceinline__ void issue_panel(Smem& sm, int p, int tid) {
    const unsigned* src;
    int words;
    if (p < 12)      { src = g_Wp1 + p * PANEL_BIG;        words = PANEL_BIG; }
    else if (p < 20) { src = g_Wp2 + (p - 12) * PANEL_BIG; words = PANEL_BIG; }
    else             { src = g_Wp3 + (p - 20) * PANEL_SM;  words = PANEL_SM;  }
    unsigned dstb = (unsigned)__cvta_generic_to_shared(sm.Wp[p & 1]);
    for (int i = tid * 4; i < words; i += NTH * 4) {
        asm volatile("cp.async.cg.shared.global [%0], [%1], 16;"
                     :: "r"(dstb + (unsigned)i * 4u), "l"(src + i));
    }
    asm volatile("cp.async.commit_group;");
}
#define CPWAIT(N) asm volatile("cp.async.wait_group %0;" :: "n"(N))

// ---------------- 64x64 warp-tile mma over one 32-K chunk -----------------
// A and B both stored as tf32 bits; split into two 16-K halves so A-fragment
// registers stay at 32 (acc 128 + a 32 + b 4 fits the RF).
template <int NT>
__device__ __forceinline__ void mma_chunk3(const unsigned* __restrict__ Ab, int lda,
                                           const unsigned* __restrict__ Bp, int nbase,
                                           float acc[4][NT][4], int lane, int wm) {
    const int lr = lane >> 2, lc = lane & 3;
#pragma unroll
    for (int half = 0; half < 2; half++) {
        unsigned a[4][2][4];
#pragma unroll
        for (int mt = 0; mt < 4; mt++)
#pragma unroll
            for (int h = 0; h < 2; h++) {
                int row = wm + mt * 16 + h * 8 + lr;
                uint4 v = *reinterpret_cast<const uint4*>(Ab + row * lda + lc * 8 + half * 4);
                a[mt][h][0] = v.x; a[mt][h][1] = v.y; a[mt][h][2] = v.z; a[mt][h][3] = v.w;
            }
#pragma unroll
        for (int nt = 0; nt < NT; nt++) {
            const unsigned* bp = Bp + (nbase + nt * 8 + lr) * PW + lc * 8 + half * 4;
            uint4 b = *reinterpret_cast<const uint4*>(bp);
            unsigned bb[4] = {b.x, b.y, b.z, b.w};
#pragma unroll
            for (int ks = 0; ks < 2; ks++) {
#pragma unroll
                for (int mt = 0; mt < 4; mt++)
                    mma8(acc[mt][nt],
                         a[mt][0][2 * ks], a[mt][1][2 * ks],
                         a[mt][0][2 * ks + 1], a[mt][1][2 * ks + 1],
                         bb[2 * ks], bb[2 * ks + 1]);
            }
        }
    }
}

// position of true column c within a permuted 256-wide row
__device__ __forceinline__ int permpos(int c) {
    return (c & ~31) + ((c & 3) << 3) + ((c & 31) >> 2);
}

// per-row partial stats from accumulators (includes bias); reduce over lc lanes
__device__ __forceinline__ void stats_from_acc(Smem& sm, float acc[4][8][4],
                                               const float* __restrict__ bias,
                                               int wm, int wn, int wcol, int lane) {
    const int lr = lane >> 2, lc = lane & 3;
#pragma unroll
    for (int mt = 0; mt < 4; mt++)
#pragma unroll
        for (int h = 0; h < 2; h++) {
            float s = 0.f, s2 = 0.f;
#pragma unroll
            for (int nt = 0; nt < 8; nt++) {
                int c = wn + nt * 8 + 2 * lc;
                float v0 = acc[mt][nt][2 * h]     + bias[c];
                float v1 = acc[mt][nt][2 * h + 1] + bias[c + 1];
                s += v0 + v1; s2 += v0 * v0 + v1 * v1;
            }
            s  += __shfl_xor_sync(0xffffffffu, s, 1);
            s2 += __shfl_xor_sync(0xffffffffu, s2, 1);
            s  += __shfl_xor_sync(0xffffffffu, s, 2);
            s2 += __shfl_xor_sync(0xffffffffu, s2, 2);
            if (lc == 0) {
                int row = wm + mt * 16 + h * 8 + lr;
                sm.red[row][wcol][0] = s;
                sm.red[row][wcol][1] = s2;
            }
        }
}

// write LN(acc+bias)*g+be, ReLU'd, PRE-ROUNDED to tf32 bits, into H (permuted)
__device__ __forceinline__ void store_h_ln(Smem& sm, float acc[4][8][4],
                                           const float* __restrict__ bias,
                                           const float* __restrict__ g,
                                           const float* __restrict__ be,
                                           int wm, int wn, int lane) {
    const int lr = lane >> 2, lc = lane & 3;
    unsigned* Hu = reinterpret_cast<unsigned*>(sm.H);
#pragma unroll
    for (int mt = 0; mt < 4; mt++)
#pragma unroll
        for (int h = 0; h < 2; h++) {
            int row = wm + mt * 16 + h * 8 + lr;
            float s  = sm.red[row][0][0] + sm.red[row][1][0] + sm.red[row][2][0] + sm.red[row][3][0];
            float s2 = sm.red[row][0][1] + sm.red[row][1][1] + sm.red[row][2][1] + sm.red[row][3][1];
            float mu  = s * (1.f / 256.f);
            float var = fmaxf(s2 * (1.f / 256.f) - mu * mu, 0.f);
            float rsd = rsqrtf(var + 1e-5f);
            unsigned* Hrow = Hu + row * SH_LD;
#pragma unroll
            for (int nt = 0; nt < 8; nt++) {
                int c = wn + nt * 8 + 2 * lc;
                int p0 = permpos(c);
                float v0 = (acc[mt][nt][2 * h]     + bias[c]     - mu) * rsd * g[c]     + be[c];
                float v1 = (acc[mt][nt][2 * h + 1] + bias[c + 1] - mu) * rsd * g[c + 1] + be[c + 1];
                Hrow[p0]     = f2tf32(fmaxf(v0, 0.f));
                Hrow[p0 + 8] = f2tf32(fmaxf(v1, 0.f));
            }
        }
}

__global__ void __launch_bounds__(NTH, 1)
edge_mlp_kernel(const float* __restrict__ src, const float* __restrict__ dst,
                const float* __restrict__ ea, const float* __restrict__ u,
                const void* __restrict__ batch_raw, const float* __restrict__ wind,
                const float* __restrict__ Ww, const float* __restrict__ bw,
                const float* __restrict__ gw, const float* __restrict__ betaw,
                const float* __restrict__ b1, const float* __restrict__ g1,
                const float* __restrict__ beta1,
                const float* __restrict__ b2, const float* __restrict__ g2,
                const float* __restrict__ beta2,
                const float* __restrict__ b3,
                float* __restrict__ out) {
    extern __shared__ char smem_raw[];
    Smem& sm = *reinterpret_cast<Smem*>(smem_raw);

    const int tid  = threadIdx.x;
    const int lane = tid & 31;
    const int warp = tid >> 5;          // 0..7
    const int wm   = (warp >> 2) * 64;  // warp row base (0 / 64)
    const int wcol = warp & 3;          // warp col (0..3)
    const long long base = (long long)blockIdx.x * MT;

    // prefetch first two weight panels immediately
    issue_panel(sm, 0, tid);
    issue_panel(sm, 1, tid);

    if (tid == 0) {
        const unsigned* p = reinterpret_cast<const unsigned*>(batch_raw);
        int f = 1;
        for (int i = 0; i < 64; i++)
            if (p[2 * i + 1] != 0u) { f = 0; break; }
        sm.is64 = f;
    }
    for (int i = tid; i < 256; i += NTH) sm.Ww[i] = Ww[i];
    for (int i = tid; i < 128; i += NTH) { sm.bw[i] = bw[i]; sm.gw[i] = gw[i]; sm.betaw[i] = betaw[i]; }
    for (int i = tid; i < 256; i += NTH) {
        sm.b1[i] = b1[i]; sm.g1[i] = g1[i]; sm.be1[i] = beta1[i];
        sm.b2[i] = b2[i]; sm.g2[i] = g2[i]; sm.be2[i] = beta2[i];
    }
    for (int i = tid; i < 64; i += NTH) sm.b3[i] = b3[i];
    __syncthreads();

    const int is64 = sm.is64;
    for (int r = tid; r < MT; r += NTH) {
        long long e = base + r;
        if (e < E_TOTAL) {
            sm.batch[r] = is64 ? (int)reinterpret_cast<const long long*>(batch_raw)[e]
                               : reinterpret_cast<const int*>(batch_raw)[e];
            sm.w0[r] = wind[2 * e];
            sm.w1[r] = wind[2 * e + 1];
        } else { sm.batch[r] = 0; sm.w0[r] = 0.f; sm.w1[r] = 0.f; }
    }
    __syncthreads();

    // winding-MLP LN stats (2 threads per row)
    {
        const int r = tid >> 1, q = tid & 1;
        const float a0 = sm.w0[r], a1 = sm.w1[r];
        float s = 0.f, s2 = 0.f;
#pragma unroll 4
        for (int jj = 0; jj < 64; jj++) {
            int j = q * 64 + jj;
            float t = fmaf(a0, sm.Ww[j], fmaf(a1, sm.Ww[128 + j], sm.bw[j]));
            s += t; s2 += t * t;
        }
        s  += __shfl_xor_sync(0xffffffffu, s, 1);
        s2 += __shfl_xor_sync(0xffffffffu, s2, 1);
        float mu  = s * (1.f / 128.f);
        float var = fmaxf(s2 * (1.f / 128.f) - mu * mu, 0.f);
        if (q == 0) { sm.mu[r] = mu; sm.rs[r] = rsqrtf(var + 1e-5f); }
    }
    __syncthreads();

    // ---- layer-1 A staging (permuted + tf32 bits), double-buffered over H ----
    auto stageA = [&](int seg) {
        unsigned* A = reinterpret_cast<unsigned*>(sm.H) + (seg & 1) * (MT * SA_LD);
        for (int i = tid; i < MT * 64; i += NTH) {
            int r = i >> 6, c = i & 63;
            long long e = base + r;
            float v = 0.f;
            if (e < E_TOTAL) {
                if (seg == 0)      v = src[e * 64 + c];
                else if (seg == 1) v = dst[e * 64 + c];
                else if (seg == 2) v = ea[e * 64 + c];
                else if (seg == 3) v = u[sm.batch[r] * 64 + c];
                else {
                    int j = c + (seg - 4) * 64;
                    float t = fmaf(sm.w0[r], sm.Ww[j], fmaf(sm.w1[r], sm.Ww[128 + j], sm.bw[j]));
                    v = fmaxf((t - sm.mu[r]) * sm.rs[r] * sm.gw[j] + sm.betaw[j], 0.f);
                }
            }
            int pos = (c & 32) + ((c & 3) << 3) + ((c & 31) >> 2);
            A[r * SA_LD + pos] = f2tf32(v);
        }
    };
    stageA(0);
    stageA(1);

    float acc[4][8][4];

    // =============== Layer 1: K=384, 12 chunks ===============
#pragma unroll
    for (int mt = 0; mt < 4; mt++)
#pragma unroll
        for (int nt = 0; nt < 8; nt++)
#pragma unroll
            for (int k = 0; k < 4; k++) acc[mt][nt][k] = 0.f;

    for (int t = 0; t < 12; t++) {
        CPWAIT(1);
        __syncthreads();
        const unsigned* Ab = reinterpret_cast<const unsigned*>(sm.H)
                             + ((t >> 1) & 1) * (MT * SA_LD) + (t & 1) * 32;
        mma_chunk3<8>(Ab, SA_LD, sm.Wp[t & 1], wcol * 64, acc, lane, wm);
        __syncthreads();
        issue_panel(sm, t + 2, tid);
        if ((t & 1) && ((t >> 1) + 2) <= 5) stageA((t >> 1) + 2);
    }
    stats_from_acc(sm, acc, sm.b1, wm, wcol * 64, wcol, lane);
    __syncthreads();
    store_h_ln(sm, acc, sm.b1, sm.g1, sm.be1, wm, wcol * 64, lane);
    __syncthreads();

    // =============== Layer 2: K=256, 8 chunks ===============
#pragma unroll
    for (int mt = 0; mt < 4; mt++)
#pragma unroll
        for (int nt = 0; nt < 8; nt++)
#pragma unroll
            for (int k = 0; k < 4; k++) acc[mt][nt][k] = 0.f;

    for (int t = 0; t < 8; t++) {
        int p = 12 + t;
        CPWAIT(1);
        __syncthreads();
        const unsigned* Ab = reinterpret_cast<const unsigned*>(sm.H) + t * 32;
        mma_chunk3<8>(Ab, SH_LD, sm.Wp[p & 1], wcol * 64, acc, lane, wm);
        __syncthreads();
        issue_panel(sm, p + 2, tid);
    }
    stats_from_acc(sm, acc, sm.b2, wm, wcol * 64, wcol, lane);
    __syncthreads();
    store_h_ln(sm, acc, sm.b2, sm.g2, sm.be2, wm, wcol * 64, lane);
    __syncthreads();

    // =============== Layer 3: K=256, N=64, 8 chunks ===============
    float acc3[4][2][4];
#pragma unroll
    for (int mt = 0; mt < 4; mt++)
#pragma unroll
        for (int nt = 0; nt < 2; nt++)
#pragma unroll
            for (int k = 0; k < 4; k++) acc3[mt][nt][k] = 0.f;

    for (int t = 0; t < 8; t++) {
        int p = 20 + t;
        if (p == 27) { CPWAIT(0); } else { CPWAIT(1); }
        __syncthreads();
        const unsigned* Ab = reinterpret_cast<const unsigned*>(sm.H) + t * 32;
        mma_chunk3<2>(Ab, SH_LD, sm.Wp[p & 1], wcol * 16, acc3, lane, wm);
        __syncthreads();
        if (p + 2 < 28) issue_panel(sm, p + 2, tid);
    }
    // stage output (unpermuted, stride SA_LD) over H, then coalesced float4 store
    {
        const int lr = lane >> 2, lc = lane & 3;
#pragma unroll
        for (int mt = 0; mt < 4; mt++)
#pragma unroll
            for (int nt = 0; nt < 2; nt++) {
                int c = wcol * 16 + nt * 8 + 2 * lc;
#pragma unroll
                for (int h = 0; h < 2; h++) {
                    int r = wm + mt * 16 + lr + h * 8;
                    sm.H[r * SA_LD + c]     = acc3[mt][nt][2 * h]     + sm.b3[c];
                    sm.H[r * SA_LD + c + 1] = acc3[mt][nt][2 * h + 1] + sm.b3[c + 1];
                }
            }
    }
    __syncthreads();
    for (int i = tid; i < MT * 16; i += NTH) {
        int r = i >> 4, c4 = i & 15;
        long long e = base + r;
        if (e < E_TOTAL) {
            float4 v = *reinterpret_cast<const float4*>(sm.H + r * SA_LD + c4 * 4);
            *reinterpret_cast<float4*>(out + e * 64 + c4 * 4) = v;
        }
    }
}

extern "C" void kernel_launch(void* const* d_in, const int* in_sizes, int n_in,
                              void* d_out, int out_size) {
    const float* src    = (const float*)d_in[0];
    const float* dst    = (const float*)d_in[1];
    const float* ea     = (const float*)d_in[2];
    const float* u      = (const float*)d_in[3];
    const void*  batch  = d_in[4];
    const float* wind   = (const float*)d_in[5];
    const float* Ww     = (const float*)d_in[6];
    const float* bw     = (const float*)d_in[7];
    const float* gw     = (const float*)d_in[8];
    const float* betaw  = (const float*)d_in[9];
    const float* W1     = (const float*)d_in[10];
    const float* b1     = (const float*)d_in[11];
    const float* g1     = (const float*)d_in[12];
    const float* beta1  = (const float*)d_in[13];
    const float* W2     = (const float*)d_in[14];
    const float* b2     = (const float*)d_in[15];
    const float* g2     = (const float*)d_in[16];
    const float* beta2  = (const float*)d_in[17];
    const float* W3     = (const float*)d_in[18];
    const float* b3     = (const float*)d_in[19];
    float* out = (float*)d_out;

    prep_kernel<<<296, 256>>>(W1, W2, W3);

    const int smem = (int)sizeof(Smem);
    cudaFuncSetAttribute(edge_mlp_kernel, cudaFuncAttributeMaxDynamicSharedMemorySize, smem);
    const int grid = (E_TOTAL + MT - 1) / MT;
    edge_mlp_kernel<<<grid, NTH, smem>>>(src, dst, ea, u, batch, wind,
                                         Ww, bw, gw, betaw,
                                         b1, g1, beta1,
                                         b2, g2, beta2,
                                         b3, out);
}